// round 17
// baseline (speedup 1.0000x reference)
#include <cuda_runtime.h>
#include <cuda_fp16.h>
#include <cstdint>

#define Tq   1024
#define F_IN 64
#define HDIM 40
#define G4   160

typedef unsigned long long ull;
typedef unsigned int uint;

// ---- global scratch (no allocation allowed; __device__ arrays) ----
__device__ float g_xa[(size_t)512 * Tq * G4];     // seq @ WaK + ba
__device__ float g_xb[(size_t)512 * Tq * G4];     // hs  @ WbK + bb
__device__ float g_hs[(size_t)512 * Tq * HDIM];   // LSTM A outputs
__device__ float g_hlast[512 * HDIM];             // LSTM B final h

// ---------------------------------------------------------------------------
// Packed f32x2 helpers
// ---------------------------------------------------------------------------
__device__ __forceinline__ ull pack2(float a, float b) {
    ull r; asm("mov.b64 %0, {%1,%2};" : "=l"(r) : "f"(a), "f"(b)); return r;
}
__device__ __forceinline__ void unpack2(ull v, float& a, float& b) {
    asm("mov.b64 {%0,%1}, %2;" : "=f"(a), "=f"(b) : "l"(v));
}
__device__ __forceinline__ void ffma2(ull& d, ull a, ull b) {
    asm("fma.rn.f32x2 %0, %1, %2, %0;" : "+l"(d) : "l"(a), "l"(b));
}

// ---------------------------------------------------------------------------
// MUFU activations
// ---------------------------------------------------------------------------
__device__ __forceinline__ float sigmoid_f(float x) {
    float e, r;
    asm("ex2.approx.f32 %0, %1;" : "=f"(e) : "f"(-1.4426950408889634f * x));
    asm("rcp.approx.f32 %0, %1;" : "=f"(r) : "f"(1.0f + e));
    return r;
}
__device__ __forceinline__ float tanh_f(float x) {
    float e, r;
    asm("ex2.approx.f32 %0, %1;" : "=f"(e) : "f"(2.8853900817779268f * x));
    asm("rcp.approx.f32 %0, %1;" : "=f"(r) : "f"(1.0f + e));
    return 1.0f - 2.0f * r;
}
__device__ __forceinline__ float gate_act(float z, float mm, float aa, float bb) {
    float e, r;
    asm("ex2.approx.f32 %0, %1;" : "=f"(e) : "f"(mm * z));
    asm("rcp.approx.f32 %0, %1;" : "=f"(r) : "f"(1.0f + e));
    return fmaf(aa, r, bb);
}

__device__ __forceinline__ unsigned smem_u32(const void* p) {
    return (unsigned)__cvta_generic_to_shared(p);
}

// ---------------------------------------------------------------------------
// Tensor-core helpers (verified R16): m16n8k16 fp16 MMA, split-fp16.
// ---------------------------------------------------------------------------
__device__ __forceinline__ void mma16816(float& c0, float& c1, float& c2, float& c3,
                                         uint a0, uint a1, uint a2, uint a3,
                                         uint b0, uint b1) {
    asm volatile(
        "mma.sync.aligned.m16n8k16.row.col.f32.f16.f16.f32 "
        "{%0,%1,%2,%3}, {%4,%5,%6,%7}, {%8,%9}, {%0,%1,%2,%3};"
        : "+f"(c0), "+f"(c1), "+f"(c2), "+f"(c3)
        : "r"(a0), "r"(a1), "r"(a2), "r"(a3), "r"(b0), "r"(b1));
}

__device__ __forceinline__ void split_pack(float x, float y, uint& hi, uint& lo) {
    __half hx = __float2half_rn(x), hy = __float2half_rn(y);
    __half lx = __float2half_rn(x - __half2float(hx));
    __half ly = __float2half_rn(y - __half2float(hy));
    __half2 H = __halves2half2(hx, hy), L = __halves2half2(lx, ly);
    hi = *reinterpret_cast<uint*>(&H);
    lo = *reinterpret_cast<uint*>(&L);
}

// ===========================================================================
// K1: xa = seq @ WaK + ba via split-fp16 HMMA.  (verified R16)
// ===========================================================================
__global__ void __launch_bounds__(160)
xa_mma(const float* __restrict__ seq, const float* __restrict__ WaK,
       const float* __restrict__ ba)
{
    __shared__ __half sxh[64 * 72];
    __shared__ __half sxl[64 * 72];
    const int b = blockIdx.x, t0 = blockIdx.y * 64;
    const int tid = threadIdx.x, w = tid >> 5, lane = tid & 31;
    const int gID = lane >> 2, tq = lane & 3;
    const int g0 = w * 32;

    for (int idx = tid; idx < 64 * 64; idx += 160) {
        const int r = idx >> 6, cx = idx & 63;
        const float v = seq[((size_t)b * Tq + t0 + r) * F_IN + cx];
        const __half h = __float2half_rn(v);
        sxh[r * 72 + cx] = h;
        sxl[r * 72 + cx] = __float2half_rn(v - __half2float(h));
    }

    uint whi[2][4][4], wlo[2][4][4];
    #pragma unroll
    for (int mt = 0; mt < 2; mt++)
    #pragma unroll
    for (int ks = 0; ks < 4; ks++) {
        const int gc = g0 + mt * 16 + gID;
        const int k0 = ks * 16 + tq * 2;
        split_pack(WaK[k0 * G4 + gc],           WaK[(k0 + 1) * G4 + gc],
                   whi[mt][ks][0], wlo[mt][ks][0]);
        split_pack(WaK[k0 * G4 + gc + 8],       WaK[(k0 + 1) * G4 + gc + 8],
                   whi[mt][ks][1], wlo[mt][ks][1]);
        split_pack(WaK[(k0 + 8) * G4 + gc],     WaK[(k0 + 9) * G4 + gc],
                   whi[mt][ks][2], wlo[mt][ks][2]);
        split_pack(WaK[(k0 + 8) * G4 + gc + 8], WaK[(k0 + 9) * G4 + gc + 8],
                   whi[mt][ks][3], wlo[mt][ks][3]);
    }
    const float bias00 = ba[g0 + gID],      bias01 = ba[g0 + gID + 8];
    const float bias10 = ba[g0 + 16 + gID], bias11 = ba[g0 + 16 + gID + 8];
    __syncthreads();

    #pragma unroll
    for (int nt = 0; nt < 8; nt++) {
        float c[2][4];
        c[0][0] = c[0][1] = bias00; c[0][2] = c[0][3] = bias01;
        c[1][0] = c[1][1] = bias10; c[1][2] = c[1][3] = bias11;
        const int row = nt * 8 + gID;
        #pragma unroll
        for (int ks = 0; ks < 4; ks++) {
            const int cw = ks * 16 + tq * 2;
            const uint bh0 = *(const uint*)&sxh[row * 72 + cw];
            const uint bh1 = *(const uint*)&sxh[row * 72 + cw + 8];
            const uint bl0 = *(const uint*)&sxl[row * 72 + cw];
            const uint bl1 = *(const uint*)&sxl[row * 72 + cw + 8];
            #pragma unroll
            for (int mt = 0; mt < 2; mt++) {
                mma16816(c[mt][0], c[mt][1], c[mt][2], c[mt][3],
                         whi[mt][ks][0], whi[mt][ks][1], whi[mt][ks][2], whi[mt][ks][3],
                         bh0, bh1);
                mma16816(c[mt][0], c[mt][1], c[mt][2], c[mt][3],
                         whi[mt][ks][0], whi[mt][ks][1], whi[mt][ks][2], whi[mt][ks][3],
                         bl0, bl1);
                mma16816(c[mt][0], c[mt][1], c[mt][2], c[mt][3],
                         wlo[mt][ks][0], wlo[mt][ks][1], wlo[mt][ks][2], wlo[mt][ks][3],
                         bh0, bh1);
            }
        }
        const int tc = t0 + nt * 8 + tq * 2;
        #pragma unroll
        for (int mt = 0; mt < 2; mt++) {
            const int gr = g0 + mt * 16 + gID;
            float* o = g_xa + ((size_t)b * Tq + tc) * G4 + gr;
            o[0]      = c[mt][0];
            o[G4]     = c[mt][1];
            o[8]      = c[mt][2];
            o[G4 + 8] = c[mt][3];
        }
    }
}

// ===========================================================================
// K3: xb = hs @ WbK + bb via split-fp16 HMMA.  (verified R16)
// ===========================================================================
__global__ void __launch_bounds__(160)
xb_mma(const float* __restrict__ WbK, const float* __restrict__ bb)
{
    __shared__ __half sxh[64 * 56];
    __shared__ __half sxl[64 * 56];
    const int b = blockIdx.x, t0 = blockIdx.y * 64;
    const int tid = threadIdx.x, w = tid >> 5, lane = tid & 31;
    const int gID = lane >> 2, tq = lane & 3;
    const int g0 = w * 32;

    for (int idx = tid; idx < 64 * 48; idx += 160) {
        const int r = idx / 48, cx = idx % 48;
        float v = 0.0f;
        if (cx < HDIM)
            v = g_hs[((size_t)b * Tq + t0 + r) * HDIM + cx];
        const __half h = __float2half_rn(v);
        sxh[r * 56 + cx] = h;
        sxl[r * 56 + cx] = __float2half_rn(v - __half2float(h));
    }

    uint whi[2][3][4], wlo[2][3][4];
    #pragma unroll
    for (int mt = 0; mt < 2; mt++)
    #pragma unroll
    for (int ks = 0; ks < 3; ks++) {
        const int gc = g0 + mt * 16 + gID;
        const int k0 = ks * 16 + tq * 2;
        #pragma unroll
        for (int fi = 0; fi < 4; fi++) {
            const int kk = k0 + ((fi >= 2) ? 8 : 0);
            const int gg = gc + ((fi & 1) ? 8 : 0);
            const float p = (kk     < HDIM) ? WbK[kk * G4 + gg]       : 0.0f;
            const float q = (kk + 1 < HDIM) ? WbK[(kk + 1) * G4 + gg] : 0.0f;
            split_pack(p, q, whi[mt][ks][fi], wlo[mt][ks][fi]);
        }
    }
    const float bias00 = bb[g0 + gID],      bias01 = bb[g0 + gID + 8];
    const float bias10 = bb[g0 + 16 + gID], bias11 = bb[g0 + 16 + gID + 8];
    __syncthreads();

    #pragma unroll
    for (int nt = 0; nt < 8; nt++) {
        float c[2][4];
        c[0][0] = c[0][1] = bias00; c[0][2] = c[0][3] = bias01;
        c[1][0] = c[1][1] = bias10; c[1][2] = c[1][3] = bias11;
        const int row = nt * 8 + gID;
        #pragma unroll
        for (int ks = 0; ks < 3; ks++) {
            const int cw = ks * 16 + tq * 2;
            const uint bh0 = *(const uint*)&sxh[row * 56 + cw];
            const uint bh1 = *(const uint*)&sxh[row * 56 + cw + 8];
            const uint bl0 = *(const uint*)&sxl[row * 56 + cw];
            const uint bl1 = *(const uint*)&sxl[row * 56 + cw + 8];
            #pragma unroll
            for (int mt = 0; mt < 2; mt++) {
                mma16816(c[mt][0], c[mt][1], c[mt][2], c[mt][3],
                         whi[mt][ks][0], whi[mt][ks][1], whi[mt][ks][2], whi[mt][ks][3],
                         bh0, bh1);
                mma16816(c[mt][0], c[mt][1], c[mt][2], c[mt][3],
                         whi[mt][ks][0], whi[mt][ks][1], whi[mt][ks][2], whi[mt][ks][3],
                         bl0, bl1);
                mma16816(c[mt][0], c[mt][1], c[mt][2], c[mt][3],
                         wlo[mt][ks][0], wlo[mt][ks][1], wlo[mt][ks][2], wlo[mt][ks][3],
                         bh0, bh1);
            }
        }
        const int tc = t0 + nt * 8 + tq * 2;
        #pragma unroll
        for (int mt = 0; mt < 2; mt++) {
            const int gr = g0 + mt * 16 + gID;
            float* o = g_xb + ((size_t)b * Tq + tc) * G4 + gr;
            o[0]      = c[mt][0];
            o[G4]     = c[mt][1];
            o[8]      = c[mt][2];
            o[G4 + 8] = c[mt][3];
        }
    }
}

// ===========================================================================
// K2/K4: BARRIER-FREE warp-per-row LSTM recurrence.
// grid 512, block 32 (one warp = one batch row). Lane l owns gate columns
// 5l..5l+4: weights 100 f32x2 in registers; h read via broadcast LDS.128
// from per-row smem. Gate exchange via shfl_xor 8/16/24 (col 5l+m keeps the
// i/f/g/o lane mapping). Lanes 0-7 update 5 units each. NO __syncthreads —
// only __syncwarp; independent warps across the SM hide each other's latency.
// Ring cp.async is warp-private (lane l: chunk l; lanes 0-7 also chunk 32+l).
// MODE 0: g_xa -> g_hs.  MODE 1: g_xb -> g_hlast.
// ===========================================================================
template<int MODE>
__global__ void __launch_bounds__(32)
recur_w(const float* __restrict__ Wr)
{
    __shared__ __align__(16) float sxa[8][G4];   // cp.async ring
    __shared__ __align__(16) float sh[2][HDIM];  // double-buffered h

    const int b = blockIdx.x, l = threadIdx.x;

    // per-lane weights: 5 columns x 20 f32x2 pairs
    ull w2[5][20];
    #pragma unroll
    for (int m = 0; m < 5; m++) {
        const int colm = 5 * l + m;
        #pragma unroll
        for (int p = 0; p < 20; p++)
            w2[m][p] = pack2(Wr[(2 * p) * G4 + colm], Wr[(2 * p + 1) * G4 + colm]);
    }

    // per-column activation constants (g-gate = cols 80..119 -> tanh)
    const float L1 = -1.4426950408889634f, L2 = -2.8853900817779268f;
    float mmv[5], aav[5], bbv[5];
    #pragma unroll
    for (int m = 0; m < 5; m++) {
        const int colm = 5 * l + m;
        const bool isG = (colm >= 80 && colm < 120);
        mmv[m] = isG ? L2 : L1;
        aav[m] = isG ? 2.0f : 1.0f;
        bbv[m] = isG ? -1.0f : 0.0f;
    }

    float cst[5] = {0.f, 0.f, 0.f, 0.f, 0.f};
    if (l < 8) {
        #pragma unroll
        for (int m = 0; m < 5; m++) sh[0][5 * l + m] = 0.0f;
    }

    const float* src = (MODE == 0 ? g_xa : g_xb) + (size_t)b * Tq * G4;

    // ring prologue: slots 0..3, one commit per slot (per-thread groups)
    #pragma unroll
    for (int p = 0; p < 4; p++) {
        unsigned d0 = smem_u32(&sxa[p][l * 4]);
        asm volatile("cp.async.ca.shared.global [%0], [%1], 16;"
                     :: "r"(d0), "l"(src + (size_t)p * G4 + l * 4));
        if (l < 8) {
            unsigned d1 = smem_u32(&sxa[p][(32 + l) * 4]);
            asm volatile("cp.async.ca.shared.global [%0], [%1], 16;"
                         :: "r"(d1), "l"(src + (size_t)p * G4 + (32 + l) * 4));
        }
        asm volatile("cp.async.commit_group;");
    }
    asm volatile("cp.async.wait_group 3;");   // slot 0 ready
    __syncwarp();

    for (int t = 0; t < Tq; t++) {
        // prefetch slot t+4; commit every iter (exact group accounting)
        {
            const int tf = t + 4;
            if (tf < Tq) {
                unsigned d0 = smem_u32(&sxa[tf & 7][l * 4]);
                asm volatile("cp.async.ca.shared.global [%0], [%1], 16;"
                             :: "r"(d0), "l"(src + (size_t)tf * G4 + l * 4));
                if (l < 8) {
                    unsigned d1 = smem_u32(&sxa[tf & 7][(32 + l) * 4]);
                    asm volatile("cp.async.ca.shared.global [%0], [%1], 16;"
                                 :: "r"(d1), "l"(src + (size_t)tf * G4 + (32 + l) * 4));
                }
            }
            asm volatile("cp.async.commit_group;\n\t"
                         "cp.async.wait_group 3;\n");   // slots <= t+1 done
        }
        __syncwarp();

        // xz for 5 columns (stride-5 word pattern: conflict-free per m)
        float xz[5];
        #pragma unroll
        for (int m = 0; m < 5; m++) xz[m] = sxa[t & 7][5 * l + m];

        // 5 dots over h (broadcast LDS.128, 100 FFMA2, 5 indep chains)
        const ulonglong2* h2 = (const ulonglong2*)sh[t & 1];
        ull acc[5] = {0ull, 0ull, 0ull, 0ull, 0ull};
        #pragma unroll
        for (int p = 0; p < 10; p++) {
            const ulonglong2 hv = h2[p];
            #pragma unroll
            for (int m = 0; m < 5; m++) {
                ffma2(acc[m], w2[m][2 * p],     hv.x);
                ffma2(acc[m], w2[m][2 * p + 1], hv.y);
            }
        }

        float v[5];
        #pragma unroll
        for (int m = 0; m < 5; m++) {
            float lo, hi;
            unpack2(acc[m], lo, hi);
            v[m] = gate_act(xz[m] + lo + hi, mmv[m], aav[m], bbv[m]);
        }

        // gate exchange: unit j = 5l+m (l<8); f,g,o at lanes l+8, l+16, l+24
        float fv[5], gv[5], ov[5];
        #pragma unroll
        for (int m = 0; m < 5; m++) {
            fv[m] = __shfl_xor_sync(0xffffffffu, v[m], 8);
            gv[m] = __shfl_xor_sync(0xffffffffu, v[m], 16);
            ov[m] = __shfl_xor_sync(0xffffffffu, v[m], 24);
        }

        if (l < 8) {
            #pragma unroll
            for (int m = 0; m < 5; m++) {
                cst[m] = fmaf(fv[m], cst[m], v[m] * gv[m]);
                const float h = ov[m] * tanh_f(cst[m]);
                sh[(t + 1) & 1][5 * l + m] = h;
                if (MODE == 0)
                    g_hs[((size_t)b * Tq + t) * HDIM + 5 * l + m] = h;
                else if (t == Tq - 1)
                    g_hlast[b * HDIM + 5 * l + m] = h;
            }
        }
        __syncwarp();
    }
}

// ===========================================================================
// K5: dense tail. grid 128 x 160 threads, 4 rows/block.  (verified R10)
// ===========================================================================
__global__ void __launch_bounds__(160)
tail_k(const float* __restrict__ feat,
       const float* __restrict__ Wg, const float* __restrict__ bg,
       const float* __restrict__ Wh, const float* __restrict__ bh,
       const float* __restrict__ Wc, const float* __restrict__ bc,
       const float* __restrict__ Wd, const float* __restrict__ bd,
       const float* __restrict__ Wo, const float* __restrict__ bo,
       float* __restrict__ out)
{
    __shared__ float hB[4][HDIM];
    __shared__ float t1[4][10], yy[4][10], cc[4][20], dd[4][10];
    const int tid = threadIdx.x, b4 = blockIdx.x * 4;
    const int r = tid / HDIM, uu = tid % HDIM;

    hB[r][uu] = g_hlast[(b4 + r) * HDIM + uu];
    __syncthreads();

    const float* fb = feat + (size_t)(b4 + r) * F_IN;
    if (uu < 10) {
        float a = bg[uu];
        #pragma unroll 8
        for (int k = 0; k < F_IN; k++) a = fmaf(fb[k], Wg[k * 10 + uu], a);
        t1[r][uu] = tanh_f(a);
    }
    __syncthreads();
    if (uu < 10) {
        float a = bh[uu];
        #pragma unroll
        for (int k = 0; k < 10; k++) a = fmaf(t1[r][k], Wh[k * 10 + uu], a);
        yy[r][uu] = tanh_f(a);
    }
    __syncthreads();
    if (uu < 20) {
        float a = bc[uu];
        #pragma unroll
        for (int k = 0; k < HDIM; k++) a = fmaf(hB[r][k], Wc[k * 20 + uu], a);
        #pragma unroll
        for (int k = 0; k < 10; k++)   a = fmaf(yy[r][k], Wc[(HDIM + k) * 20 + uu], a);
        cc[r][uu] = fmaxf(a, 0.0f);
    }
    __syncthreads();
    if (uu < 10) {
        float a = bd[uu];
        #pragma unroll
        for (int k = 0; k < 20; k++) a = fmaf(cc[r][k], Wd[k * 10 + uu], a);
        dd[r][uu] = fmaxf(a, 0.0f);
    }
    __syncthreads();
    if (uu == 0) {
        float a = bo[0];
        #pragma unroll
        for (int k = 0; k < 10; k++) a = fmaf(dd[r][k], Wo[k], a);
        out[b4 + r] = sigmoid_f(a);
    }
}

// ---------------------------------------------------------------------------
extern "C" void kernel_launch(void* const* d_in, const int* in_sizes, int n_in,
                              void* d_out, int out_size)
{
    (void)in_sizes; (void)n_in; (void)out_size;
    const float* seq  = (const float*)d_in[0];
    const float* feat = (const float*)d_in[1];
    const float* WaK  = (const float*)d_in[2];
    const float* WaR  = (const float*)d_in[3];
    const float* ba   = (const float*)d_in[4];
    const float* WbK  = (const float*)d_in[5];
    const float* WbR  = (const float*)d_in[6];
    const float* bb   = (const float*)d_in[7];
    const float* Wg   = (const float*)d_in[8];
    const float* bg   = (const float*)d_in[9];
    const float* Wh   = (const float*)d_in[10];
    const float* bh   = (const float*)d_in[11];
    const float* Wc   = (const float*)d_in[12];
    const float* bc   = (const float*)d_in[13];
    const float* Wd   = (const float*)d_in[14];
    const float* bd   = (const float*)d_in[15];
    const float* Wo   = (const float*)d_in[16];
    const float* bo   = (const float*)d_in[17];
    float* out = (float*)d_out;

    xa_mma<<<dim3(512, 16), 160>>>(seq, WaK, ba);
    recur_w<0><<<512, 32>>>(WaR);
    xb_mma<<<dim3(512, 16), 160>>>(WbK, bb);
    recur_w<1><<<512, 32>>>(WbR);
    tail_k<<<128, 160>>>(feat, Wg, bg, Wh, bh, Wc, bc, Wd, bd, Wo, bo, out);
}